// round 2
// baseline (speedup 1.0000x reference)
#include <cuda_runtime.h>
#include <cuda_bf16.h>
#include <math.h>
#include <stdint.h>

#define NROWS 8192
#define DDIM  128
#define INV_T 14.285714285714286f   // 1/0.07, also the shift C

// ---------------- device scratch (no allocations allowed) ----------------
__device__ __nv_bfloat16 g_feats[NROWS * DDIM];   // normalized bf16 features
__device__ float g_S[NROWS];                      // sum exp(l - C), j != i
__device__ float g_P[NROWS];                      // sum over positives of (l - C)
__device__ float g_cnt[NROWS];                    // positive count
__device__ int   g_labels[NROWS];

// ---------------- prep: zero accumulators + label dtype sniff ----------------
// labels may arrive as int64 (values < 100 => every odd 32-bit word is 0) or int32.
__global__ void prep_kernel(const unsigned int* __restrict__ lw) {
    __shared__ int flag;
    int t = threadIdx.x;
    if (t == 0) flag = 0;
    __syncthreads();
    int local = 0;
    for (int k = t; k < NROWS / 2; k += blockDim.x) {
        if (lw[2 * k + 1] != 0u) local = 1;     // max index 8191: safe for both dtypes
    }
    if (local) atomicOr(&flag, 1);
    __syncthreads();
    bool is64 = (flag == 0);
    for (int i = t; i < NROWS; i += blockDim.x) {
        unsigned v = is64 ? lw[2 * i] : lw[i];
        g_labels[i] = (int)v;
        g_S[i] = 0.0f;
        g_P[i] = 0.0f;
        g_cnt[i] = 0.0f;
    }
}

// ---------------- normalize rows fp32 -> bf16 ----------------
// one warp per row; 8 warps per 256-thread block
__global__ void norm_kernel(const float* __restrict__ f) {
    int warp = threadIdx.x >> 5;
    int lane = threadIdx.x & 31;
    int row = blockIdx.x * 8 + warp;
    const float4* src = (const float4*)(f + (size_t)row * DDIM);
    float4 v = src[lane];                         // 32 lanes * 4 = 128
    float ss = v.x * v.x + v.y * v.y + v.z * v.z + v.w * v.w;
    #pragma unroll
    for (int o = 16; o; o >>= 1) ss += __shfl_xor_sync(0xffffffffu, ss, o);
    float nrm = sqrtf(ss);
    float s = 1.0f / fmaxf(nrm, 1e-12f);
    __nv_bfloat162* dst = (__nv_bfloat162*)(g_feats + (size_t)row * DDIM);
    dst[lane * 2 + 0] = __floats2bfloat162_rn(v.x * s, v.y * s);
    dst[lane * 2 + 1] = __floats2bfloat162_rn(v.z * s, v.w * s);
}

// ---------------- fused GEMM + masked softmax-stats ----------------
// Block tile: 128 (i) x 128 (j), K=128 fully resident in SMEM.
// 8 warps as 4(m) x 2(n); warp tile 32x64; mma.sync m16n8k16 bf16.
// blockIdx.x -> row tile; blockIdx.y -> column split (NSPLIT splits of 8 tiles each).
#define NSPLIT 8
#define TILES_PER_SPLIT (64 / NSPLIT)

__global__ __launch_bounds__(256, 2) void gemm_kernel() {
    extern __shared__ char smem[];
    __nv_bfloat16* As = (__nv_bfloat16*)smem;              // 128x128 bf16, swizzled
    __nv_bfloat16* Bs = (__nv_bfloat16*)(smem + 32768);    // 128x128 bf16, swizzled
    int* jlab = (int*)(smem + 65536);                      // 128 ints

    const int tid  = threadIdx.x;
    const int lane = tid & 31;
    const int warp = tid >> 5;
    const int warp_m = warp >> 1;      // 0..3
    const int warp_n = warp & 1;       // 0..1
    const int groupid = lane >> 2;     // 0..7
    const int quad = lane & 3;         // 0..3

    const int iBase = blockIdx.x * 128;

    // ---- load A tile once (rows fixed for this block), XOR-16B swizzle ----
    {
        const uint4* src = (const uint4*)g_feats;   // 16B chunks, 16 per row
        uint4* dstA = (uint4*)As;
        #pragma unroll
        for (int it = 0; it < 8; it++) {
            int idx = tid + it * 256;               // 0..2047
            int r = idx >> 4, c = idx & 15;
            dstA[r * 16 + (c ^ (r & 7))] = src[(size_t)(iBase + r) * 16 + c];
        }
    }

    // labels for the 4 rows this thread owns (msub in {0,1}, row-half in {0,1})
    int labI[4];
    #pragma unroll
    for (int ms = 0; ms < 2; ms++)
        #pragma unroll
        for (int rh = 0; rh < 2; rh++)
            labI[ms * 2 + rh] = g_labels[iBase + warp_m * 32 + ms * 16 + groupid + rh * 8];

    float sS[4] = {0, 0, 0, 0};
    float sP[4] = {0, 0, 0, 0};
    float sC[4] = {0, 0, 0, 0};

    const unsigned aBase = (unsigned)__cvta_generic_to_shared(As);
    const unsigned bBase = (unsigned)__cvta_generic_to_shared(Bs);

    for (int jt = 0; jt < TILES_PER_SPLIT; jt++) {
        const int jBase = (blockIdx.y * TILES_PER_SPLIT + jt) * 128;

        __syncthreads();   // protect Bs/jlab reuse across iterations
        {
            const uint4* src = (const uint4*)g_feats;
            uint4* dstB = (uint4*)Bs;
            #pragma unroll
            for (int it = 0; it < 8; it++) {
                int idx = tid + it * 256;
                int r = idx >> 4, c = idx & 15;
                dstB[r * 16 + (c ^ (r & 7))] = src[(size_t)(jBase + r) * 16 + c];
            }
            if (tid < 128) jlab[tid] = g_labels[jBase + tid];
        }
        __syncthreads();

        float acc[2][8][4];
        #pragma unroll
        for (int ms = 0; ms < 2; ms++)
            #pragma unroll
            for (int ns = 0; ns < 8; ns++)
                #pragma unroll
                for (int e = 0; e < 4; e++) acc[ms][ns][e] = 0.0f;

        // ---- main K loop: 8 chunks of k16 ----
        #pragma unroll
        for (int kc = 0; kc < 8; kc++) {
            unsigned a_frag[2][4];
            unsigned b_frag[8][2];

            #pragma unroll
            for (int ms = 0; ms < 2; ms++) {
                int r  = warp_m * 32 + ms * 16 + (lane & 15);
                int c8 = kc * 2 + (lane >> 4);
                unsigned addr = aBase + (unsigned)((r * 16 + (c8 ^ (r & 7))) * 16);
                asm volatile(
                    "ldmatrix.sync.aligned.m8n8.x4.shared.b16 {%0,%1,%2,%3}, [%4];"
                    : "=r"(a_frag[ms][0]), "=r"(a_frag[ms][1]),
                      "=r"(a_frag[ms][2]), "=r"(a_frag[ms][3])
                    : "r"(addr));
            }
            #pragma unroll
            for (int ns = 0; ns < 8; ns++) {
                int r  = warp_n * 64 + ns * 8 + (lane & 7);
                int c8 = kc * 2 + ((lane >> 3) & 1);
                unsigned addr = bBase + (unsigned)((r * 16 + (c8 ^ (r & 7))) * 16);
                asm volatile(
                    "ldmatrix.sync.aligned.m8n8.x2.shared.b16 {%0,%1}, [%2];"
                    : "=r"(b_frag[ns][0]), "=r"(b_frag[ns][1])
                    : "r"(addr));
            }
            #pragma unroll
            for (int ms = 0; ms < 2; ms++)
                #pragma unroll
                for (int ns = 0; ns < 8; ns++) {
                    asm volatile(
                        "mma.sync.aligned.m16n8k16.row.col.f32.bf16.bf16.f32 "
                        "{%0,%1,%2,%3}, {%4,%5,%6,%7}, {%8,%9}, {%0,%1,%2,%3};"
                        : "+f"(acc[ms][ns][0]), "+f"(acc[ms][ns][1]),
                          "+f"(acc[ms][ns][2]), "+f"(acc[ms][ns][3])
                        : "r"(a_frag[ms][0]), "r"(a_frag[ms][1]),
                          "r"(a_frag[ms][2]), "r"(a_frag[ms][3]),
                          "r"(b_frag[ns][0]), "r"(b_frag[ns][1]));
                }
        }

        // ---- epilogue: exp / masks / per-row accumulation ----
        #pragma unroll
        for (int ms = 0; ms < 2; ms++) {
            int i0 = iBase + warp_m * 32 + ms * 16 + groupid;
            #pragma unroll
            for (int ns = 0; ns < 8; ns++) {
                int jl = warp_n * 64 + ns * 8 + quad * 2;
                int j0 = jBase + jl;
                int lj0 = jlab[jl];
                int lj1 = jlab[jl + 1];
                #pragma unroll
                for (int e = 0; e < 4; e++) {
                    int i  = i0 + (e >> 1) * 8;
                    int j  = j0 + (e & 1);
                    int lj = (e & 1) ? lj1 : lj0;
                    int ridx = ms * 2 + (e >> 1);
                    float lp = fmaf(acc[ms][ns][e], INV_T, -INV_T);  // (dot-1)/T
                    float ex = __expf(lp);
                    if (i != j) {
                        sS[ridx] += ex;
                        if (labI[ridx] == lj) { sP[ridx] += lp; sC[ridx] += 1.0f; }
                    }
                }
            }
        }
    }

    // ---- lane reduce (4 lanes share each row) + global atomics ----
    #pragma unroll
    for (int r = 0; r < 4; r++) {
        float s = sS[r], p = sP[r], c = sC[r];
        s += __shfl_xor_sync(0xffffffffu, s, 1);
        s += __shfl_xor_sync(0xffffffffu, s, 2);
        p += __shfl_xor_sync(0xffffffffu, p, 1);
        p += __shfl_xor_sync(0xffffffffu, p, 2);
        c += __shfl_xor_sync(0xffffffffu, c, 1);
        c += __shfl_xor_sync(0xffffffffu, c, 2);
        if (quad == 0) {
            int i = iBase + warp_m * 32 + (r >> 1) * 16 + groupid + (r & 1) * 8;
            atomicAdd(&g_S[i], s);
            atomicAdd(&g_P[i], p);
            atomicAdd(&g_cnt[i], c);
        }
    }
}

// ---------------- final loss reduction ----------------
__global__ void loss_kernel(float* __restrict__ out) {
    __shared__ float red[1024];
    int t = threadIdx.x;
    float local = 0.0f;
    for (int i = t; i < NROWS; i += 1024) {
        // mean_log_prob_pos_i = P_i/cnt_i - log(S_i + 1e-12)
        local += g_P[i] / g_cnt[i] - logf(g_S[i] + 1e-12f);
    }
    red[t] = local;
    __syncthreads();
    #pragma unroll
    for (int s = 512; s > 0; s >>= 1) {
        if (t < s) red[t] += red[t + s];
        __syncthreads();
    }
    if (t == 0) out[0] = -red[0] / (float)NROWS;
}

// ---------------- launch ----------------
extern "C" void kernel_launch(void* const* d_in, const int* in_sizes, int n_in,
                              void* d_out, int out_size) {
    const float* feats = (const float*)d_in[0];
    const unsigned int* labw = (const unsigned int*)d_in[1];

    cudaFuncSetAttribute(gemm_kernel, cudaFuncAttributeMaxDynamicSharedMemorySize,
                         65536 + 512);

    prep_kernel<<<1, 1024>>>(labw);
    norm_kernel<<<NROWS / 8, 256>>>(feats);
    dim3 grid(NROWS / 128, NSPLIT);
    gemm_kernel<<<grid, 256, 65536 + 512>>>();
    loss_kernel<<<1, 1024>>>((float*)d_out);
}

// round 3
// speedup vs baseline: 1.2509x; 1.2509x over previous
#include <cuda_runtime.h>
#include <cuda_bf16.h>
#include <math.h>
#include <stdint.h>

#define NROWS 8192
#define DDIM  128
#define INV_T 14.285714285714286f   // 1/0.07, also the shift C

// ---------------- device scratch (no allocations allowed) ----------------
__device__ __nv_bfloat16 g_feats[NROWS * DDIM];   // normalized bf16 features
__device__ float g_S[NROWS];                      // sum_{j!=i} exp(l_ij - C)
__device__ float g_P[NROWS];                      // sum over positives of (l_ij - C)
__device__ int   g_labels[NROWS];

// ---------------- fused prep + normalize (1024 blocks x 256) ----------------
// one warp per row for the normalization; threads 0..255 also sniff the label
// dtype (int64 -> odd 32-bit words of the first 512 words are all zero) and
// threads 0..7 convert this block's 8 labels + zero the accumulators.
__global__ void prep_norm_kernel(const float* __restrict__ f,
                                 const unsigned int* __restrict__ lw,
                                 float* __restrict__ out) {
    __shared__ int flag;
    int warp = threadIdx.x >> 5;
    int lane = threadIdx.x & 31;
    int row = blockIdx.x * 8 + warp;

    const float4* src = (const float4*)(f + (size_t)row * DDIM);
    float4 v = src[lane];                         // 32 lanes * 4 = 128
    float ss = v.x * v.x + v.y * v.y + v.z * v.z + v.w * v.w;
    #pragma unroll
    for (int o = 16; o; o >>= 1) ss += __shfl_xor_sync(0xffffffffu, ss, o);
    float s = 1.0f / fmaxf(sqrtf(ss), 1e-12f);
    __nv_bfloat162* dst = (__nv_bfloat162*)(g_feats + (size_t)row * DDIM);
    dst[lane * 2 + 0] = __floats2bfloat162_rn(v.x * s, v.y * s);
    dst[lane * 2 + 1] = __floats2bfloat162_rn(v.z * s, v.w * s);

    // ---- label dtype sniff over shared 512-word window ----
    if (threadIdx.x == 0) flag = 0;
    __syncthreads();
    if (lw[2 * threadIdx.x + 1] != 0u) atomicOr(&flag, 1);
    __syncthreads();
    bool is64 = (flag == 0);
    if (threadIdx.x < 8) {
        int i = blockIdx.x * 8 + threadIdx.x;
        g_labels[i] = (int)(is64 ? lw[2 * i] : lw[i]);
        g_S[i] = 0.0f;
        g_P[i] = 0.0f;
    }
    if (blockIdx.x == 0 && threadIdx.x == 0) out[0] = 0.0f;
}

// ---------------- symmetric fused GEMM + masked softmax-stats ----------------
// Only upper-triangle tiles (tj >= ti): 2080 blocks of one 128x128 tile each.
// Off-diagonal tiles accumulate BOTH row-side (anchor i) and column-side
// (anchor j, using l_ji = l_ij) statistics. 8 warps as 4(m) x 2(n),
// warp tile 32x64, mma.sync m16n8k16 bf16, K=128 resident.
__global__ __launch_bounds__(256, 2) void gemm_kernel() {
    extern __shared__ char smem[];
    __nv_bfloat16* As = (__nv_bfloat16*)smem;              // 128x128 bf16, swizzled
    __nv_bfloat16* Bs = (__nv_bfloat16*)(smem + 32768);    // 128x128 bf16, swizzled
    int*   jlab = (int*)  (smem + 65536);                  // 128 ints
    float* rS   = (float*)(smem + 66048);                  // row-side S
    float* rP   = (float*)(smem + 66560);                  // row-side P
    float* cS   = (float*)(smem + 67072);                  // col-side S
    float* cP   = (float*)(smem + 67584);                  // col-side P

    const int tid  = threadIdx.x;
    const int lane = tid & 31;
    const int warp = tid >> 5;
    const int warp_m = warp >> 1;      // 0..3
    const int warp_n = warp & 1;       // 0..1
    const int groupid = lane >> 2;     // 0..7
    const int quad = lane & 3;         // 0..3

    // ---- decode upper-triangular tile coordinates ----
    int b = blockIdx.x;
    int ti = 0, len = 64;
    while (b >= len) { b -= len; ti++; len--; }
    const int tj = ti + b;
    const bool diag = (ti == tj);
    const int iBase = ti * 128;
    const int jBase = tj * 128;

    // ---- load tiles (XOR-16B swizzle) + labels + zero stats ----
    {
        const uint4* src = (const uint4*)g_feats;   // 16B chunks, 16 per row
        uint4* dstA = (uint4*)As;
        uint4* dstB = (uint4*)Bs;
        #pragma unroll
        for (int it = 0; it < 8; it++) {
            int idx = tid + it * 256;               // 0..2047
            int r = idx >> 4, c = idx & 15;
            int cs = c ^ (r & 7);
            dstA[r * 16 + cs] = src[(size_t)(iBase + r) * 16 + c];
            dstB[r * 16 + cs] = src[(size_t)(jBase + r) * 16 + c];
        }
        if (tid < 128) {
            jlab[tid] = g_labels[jBase + tid];
            rS[tid] = 0.0f; rP[tid] = 0.0f;
            cS[tid] = 0.0f; cP[tid] = 0.0f;
        }
    }

    // labels for the 4 rows this thread owns
    int labI[4];
    #pragma unroll
    for (int ms = 0; ms < 2; ms++)
        #pragma unroll
        for (int rh = 0; rh < 2; rh++)
            labI[ms * 2 + rh] = g_labels[iBase + warp_m * 32 + ms * 16 + groupid + rh * 8];

    __syncthreads();

    const unsigned aBase = (unsigned)__cvta_generic_to_shared(As);
    const unsigned bBase = (unsigned)__cvta_generic_to_shared(Bs);

    float acc[2][8][4];
    #pragma unroll
    for (int ms = 0; ms < 2; ms++)
        #pragma unroll
        for (int ns = 0; ns < 8; ns++)
            #pragma unroll
            for (int e = 0; e < 4; e++) acc[ms][ns][e] = 0.0f;

    // ---- main K loop: 8 chunks of k16 ----
    #pragma unroll
    for (int kc = 0; kc < 8; kc++) {
        unsigned a_frag[2][4];
        unsigned b_frag[8][2];

        #pragma unroll
        for (int ms = 0; ms < 2; ms++) {
            int r  = warp_m * 32 + ms * 16 + (lane & 15);
            int c8 = kc * 2 + (lane >> 4);
            unsigned addr = aBase + (unsigned)((r * 16 + (c8 ^ (r & 7))) * 16);
            asm volatile(
                "ldmatrix.sync.aligned.m8n8.x4.shared.b16 {%0,%1,%2,%3}, [%4];"
                : "=r"(a_frag[ms][0]), "=r"(a_frag[ms][1]),
                  "=r"(a_frag[ms][2]), "=r"(a_frag[ms][3])
                : "r"(addr));
        }
        #pragma unroll
        for (int ns = 0; ns < 8; ns++) {
            int r  = warp_n * 64 + ns * 8 + (lane & 7);
            int c8 = kc * 2 + ((lane >> 3) & 1);
            unsigned addr = bBase + (unsigned)((r * 16 + (c8 ^ (r & 7))) * 16);
            asm volatile(
                "ldmatrix.sync.aligned.m8n8.x2.shared.b16 {%0,%1}, [%2];"
                : "=r"(b_frag[ns][0]), "=r"(b_frag[ns][1])
                : "r"(addr));
        }
        #pragma unroll
        for (int ms = 0; ms < 2; ms++)
            #pragma unroll
            for (int ns = 0; ns < 8; ns++) {
                asm volatile(
                    "mma.sync.aligned.m16n8k16.row.col.f32.bf16.bf16.f32 "
                    "{%0,%1,%2,%3}, {%4,%5,%6,%7}, {%8,%9}, {%0,%1,%2,%3};"
                    : "+f"(acc[ms][ns][0]), "+f"(acc[ms][ns][1]),
                      "+f"(acc[ms][ns][2]), "+f"(acc[ms][ns][3])
                    : "r"(a_frag[ms][0]), "r"(a_frag[ms][1]),
                      "r"(a_frag[ms][2]), "r"(a_frag[ms][3]),
                      "r"(b_frag[ns][0]), "r"(b_frag[ns][1]));
            }
    }

    // ---- epilogue: row-side AND column-side stats ----
    float rSreg[4] = {0, 0, 0, 0};
    float rPreg[4] = {0, 0, 0, 0};

    #pragma unroll
    for (int ns = 0; ns < 8; ns++) {
        int jl = warp_n * 64 + ns * 8 + quad * 2;
        int lj0 = jlab[jl];
        int lj1 = jlab[jl + 1];
        float cs0 = 0, cs1 = 0, cp0 = 0, cp1 = 0;
        #pragma unroll
        for (int ms = 0; ms < 2; ms++) {
            #pragma unroll
            for (int e = 0; e < 4; e++) {
                int ridx = ms * 2 + (e >> 1);
                int i = iBase + warp_m * 32 + ms * 16 + groupid + (e >> 1) * 8;
                int j = jBase + jl + (e & 1);
                int lj = (e & 1) ? lj1 : lj0;
                float lp = fmaf(acc[ms][ns][e], INV_T, -INV_T);  // (dot-1)/T
                float ex = __expf(lp);
                if (i != j) {
                    bool m = (labI[ridx] == lj);
                    rSreg[ridx] += ex;
                    if (m) rPreg[ridx] += lp;
                    if (e & 1) { cs1 += ex; if (m) cp1 += lp; }
                    else       { cs0 += ex; if (m) cp0 += lp; }
                }
            }
        }
        if (!diag) {
            // reduce over the 8 row-lanes (stride 4 within warp)
            #pragma unroll
            for (int o = 4; o <= 16; o <<= 1) {
                cs0 += __shfl_xor_sync(0xffffffffu, cs0, o);
                cs1 += __shfl_xor_sync(0xffffffffu, cs1, o);
                cp0 += __shfl_xor_sync(0xffffffffu, cp0, o);
                cp1 += __shfl_xor_sync(0xffffffffu, cp1, o);
            }
            if (groupid == 0) {
                atomicAdd(&cS[jl], cs0);     atomicAdd(&cS[jl + 1], cs1);
                atomicAdd(&cP[jl], cp0);     atomicAdd(&cP[jl + 1], cp1);
            }
        }
    }

    // row side: 4 quad-lanes share each row
    #pragma unroll
    for (int r = 0; r < 4; r++) {
        float s = rSreg[r], p = rPreg[r];
        s += __shfl_xor_sync(0xffffffffu, s, 1);
        s += __shfl_xor_sync(0xffffffffu, s, 2);
        p += __shfl_xor_sync(0xffffffffu, p, 1);
        p += __shfl_xor_sync(0xffffffffu, p, 2);
        if (quad == 0) {
            int rloc = warp_m * 32 + (r >> 1) * 16 + groupid + (r & 1) * 8;
            atomicAdd(&rS[rloc], s);
            atomicAdd(&rP[rloc], p);
        }
    }

    __syncthreads();

    if (tid < 128) {
        atomicAdd(&g_S[iBase + tid], rS[tid]);
        atomicAdd(&g_P[iBase + tid], rP[tid]);
        if (!diag) {
            atomicAdd(&g_S[jBase + tid], cS[tid]);
            atomicAdd(&g_P[jBase + tid], cP[tid]);
        }
    }
}

// ---------------- final loss reduction (16 blocks) ----------------
// positive count per row is a pure label property: cnt_i = hist[label_i] - 1
__global__ void loss_kernel(float* __restrict__ out) {
    __shared__ int hist[256];
    __shared__ float red[256];
    int t = threadIdx.x;
    hist[t] = 0;
    __syncthreads();
    for (int i = t; i < NROWS; i += 256)
        atomicAdd(&hist[g_labels[i] & 255], 1);
    __syncthreads();

    float local = 0.0f;
    int base = blockIdx.x * 512;
    for (int i = base + t; i < base + 512; i += 256) {
        float cnt = (float)(hist[g_labels[i] & 255] - 1);
        local += g_P[i] / cnt - logf(g_S[i] + 1e-12f);
    }
    red[t] = local;
    __syncthreads();
    #pragma unroll
    for (int s = 128; s > 0; s >>= 1) {
        if (t < s) red[t] += red[t + s];
        __syncthreads();
    }
    if (t == 0) atomicAdd(out, -red[0] / (float)NROWS);
}

// ---------------- launch ----------------
extern "C" void kernel_launch(void* const* d_in, const int* in_sizes, int n_in,
                              void* d_out, int out_size) {
    const float* feats = (const float*)d_in[0];
    const unsigned int* labw = (const unsigned int*)d_in[1];

    cudaFuncSetAttribute(gemm_kernel, cudaFuncAttributeMaxDynamicSharedMemorySize,
                         68096);

    prep_norm_kernel<<<NROWS / 8, 256>>>(feats, labw, (float*)d_out);
    gemm_kernel<<<2080, 256, 68096>>>();
    loss_kernel<<<16, 256>>>((float*)d_out);
}

// round 6
// speedup vs baseline: 1.3131x; 1.0497x over previous
#include <cuda_runtime.h>
#include <cuda_bf16.h>
#include <math.h>
#include <stdint.h>

#define NROWS 8192
#define DDIM  128
#define INV_T 14.285714285714286f            // 1/0.07 == shift C == row max
#define K2    20.60992915555662f             // log2(e)/0.07

// ---------------- device scratch ----------------
__device__ __nv_bfloat16 g_feats[NROWS * DDIM];   // normalized bf16 features
__device__ float g_S[NROWS];                      // sum_{j!=i} exp(l_ij - C)
__device__ float g_classSum[100 * DDIM];          // per-class feature sums
__device__ int   g_labels[NROWS];

// ---------------- prep: normalize + labels + zero accumulators ----------------
__global__ void prep_norm_kernel(const float* __restrict__ f,
                                 const unsigned int* __restrict__ lw,
                                 float* __restrict__ out) {
    __shared__ int flag;
    int warp = threadIdx.x >> 5;
    int lane = threadIdx.x & 31;
    int row = blockIdx.x * 8 + warp;

    const float4* src = (const float4*)(f + (size_t)row * DDIM);
    float4 v = src[lane];
    float ss = v.x * v.x + v.y * v.y + v.z * v.z + v.w * v.w;
    #pragma unroll
    for (int o = 16; o; o >>= 1) ss += __shfl_xor_sync(0xffffffffu, ss, o);
    float s = 1.0f / fmaxf(sqrtf(ss), 1e-12f);
    __nv_bfloat162* dst = (__nv_bfloat162*)(g_feats + (size_t)row * DDIM);
    dst[lane * 2 + 0] = __floats2bfloat162_rn(v.x * s, v.y * s);
    dst[lane * 2 + 1] = __floats2bfloat162_rn(v.z * s, v.w * s);

    // label dtype sniff: int64 -> odd 32-bit words all zero in first 512 words
    if (threadIdx.x == 0) flag = 0;
    __syncthreads();
    if (lw[2 * threadIdx.x + 1] != 0u) atomicOr(&flag, 1);
    __syncthreads();
    bool is64 = (flag == 0);
    if (threadIdx.x < 8) {
        int i = blockIdx.x * 8 + threadIdx.x;
        g_labels[i] = (int)(is64 ? lw[2 * i] : lw[i]);
        g_S[i] = 0.0f;
    }
    int gid = blockIdx.x * 256 + threadIdx.x;
    if (gid < 100 * DDIM) g_classSum[gid] = 0.0f;
    if (gid == 0) out[0] = 0.0f;
}

// ---------------- classSum: per-class feature sums (atomic) ----------------
__global__ void classsum_kernel() {
    int warp = threadIdx.x >> 5;
    int lane = threadIdx.x & 31;
    int i = blockIdx.x * 8 + warp;
    int lab = g_labels[i];
    const __nv_bfloat162* f2 = (const __nv_bfloat162*)(g_feats + (size_t)i * DDIM);
    __nv_bfloat162 a = f2[lane * 2], b = f2[lane * 2 + 1];
    float* cs = g_classSum + lab * DDIM + lane * 4;
    atomicAdd(cs + 0, __low2float(a));
    atomicAdd(cs + 1, __high2float(a));
    atomicAdd(cs + 2, __low2float(b));
    atomicAdd(cs + 3, __high2float(b));
}

// ---------------- symmetric fused GEMM + exp-sum epilogue ----------------
// Upper-triangle tiles only (2080 blocks, one 128x128 tile each). Off-diagonal
// tiles accumulate row-side S (anchor i) AND column-side S (anchor j, since
// l_ji = l_ij). 8 warps as 4(m) x 2(n); warp tile 32x64; mma.sync m16n8k16.
__global__ __launch_bounds__(256, 2) void gemm_kernel() {
    extern __shared__ char smem[];
    __nv_bfloat16* As = (__nv_bfloat16*)smem;              // 128x128 bf16, swizzled
    __nv_bfloat16* Bs = (__nv_bfloat16*)(smem + 32768);    // 128x128 bf16, swizzled
    float* rS = (float*)(smem + 65536);                    // row-side S (128)
    float* cS = (float*)(smem + 66048);                    // col-side S (128)

    const int tid  = threadIdx.x;
    const int lane = tid & 31;
    const int warp = tid >> 5;
    const int warp_m = warp >> 1;      // 0..3
    const int warp_n = warp & 1;       // 0..1
    const int groupid = lane >> 2;     // 0..7
    const int quad = lane & 3;         // 0..3

    // ---- decode upper-triangular tile coordinates ----
    int b = blockIdx.x;
    int ti = 0, len = 64;
    while (b >= len) { b -= len; ti++; len--; }
    const int tj = ti + b;
    const bool diag = (ti == tj);
    const int iBase = ti * 128;
    const int jBase = tj * 128;

    // ---- load tiles (XOR-16B swizzle) + zero stats ----
    {
        const uint4* src = (const uint4*)g_feats;   // 16B chunks, 16 per row
        uint4* dstA = (uint4*)As;
        uint4* dstB = (uint4*)Bs;
        #pragma unroll
        for (int it = 0; it < 8; it++) {
            int idx = tid + it * 256;               // 0..2047
            int r = idx >> 4, c = idx & 15;
            int cs = c ^ (r & 7);
            dstA[r * 16 + cs] = src[(size_t)(iBase + r) * 16 + c];
            dstB[r * 16 + cs] = src[(size_t)(jBase + r) * 16 + c];
        }
        if (tid < 128) { rS[tid] = 0.0f; cS[tid] = 0.0f; }
    }
    __syncthreads();

    const unsigned aBase = (unsigned)__cvta_generic_to_shared(As);
    const unsigned bBase = (unsigned)__cvta_generic_to_shared(Bs);

    float acc[2][8][4];
    #pragma unroll
    for (int ms = 0; ms < 2; ms++)
        #pragma unroll
        for (int ns = 0; ns < 8; ns++)
            #pragma unroll
            for (int e = 0; e < 4; e++) acc[ms][ns][e] = 0.0f;

    // ---- main K loop: 8 chunks of k16 ----
    #pragma unroll
    for (int kc = 0; kc < 8; kc++) {
        unsigned a_frag[2][4];
        unsigned b_frag[8][2];

        #pragma unroll
        for (int ms = 0; ms < 2; ms++) {
            int r  = warp_m * 32 + ms * 16 + (lane & 15);
            int c8 = kc * 2 + (lane >> 4);
            unsigned addr = aBase + (unsigned)((r * 16 + (c8 ^ (r & 7))) * 16);
            asm volatile(
                "ldmatrix.sync.aligned.m8n8.x4.shared.b16 {%0,%1,%2,%3}, [%4];"
                : "=r"(a_frag[ms][0]), "=r"(a_frag[ms][1]),
                  "=r"(a_frag[ms][2]), "=r"(a_frag[ms][3])
                : "r"(addr));
        }
        // B: x4 ldmatrix covering a pair of n8 tiles per load
        // lanes 0-7:(ns0,k0) 8-15:(ns0,k1) 16-23:(ns1,k0) 24-31:(ns1,k1)
        #pragma unroll
        for (int np = 0; np < 4; np++) {
            int r  = warp_n * 64 + (np * 2 + ((lane >> 4) & 1)) * 8 + (lane & 7);
            int c8 = kc * 2 + ((lane >> 3) & 1);
            unsigned addr = bBase + (unsigned)((r * 16 + (c8 ^ (r & 7))) * 16);
            asm volatile(
                "ldmatrix.sync.aligned.m8n8.x4.shared.b16 {%0,%1,%2,%3}, [%4];"
                : "=r"(b_frag[np * 2][0]), "=r"(b_frag[np * 2][1]),
                  "=r"(b_frag[np * 2 + 1][0]), "=r"(b_frag[np * 2 + 1][1])
                : "r"(addr));
        }
        #pragma unroll
        for (int ms = 0; ms < 2; ms++)
            #pragma unroll
            for (int ns = 0; ns < 8; ns++) {
                asm volatile(
                    "mma.sync.aligned.m16n8k16.row.col.f32.bf16.bf16.f32 "
                    "{%0,%1,%2,%3}, {%4,%5,%6,%7}, {%8,%9}, {%0,%1,%2,%3};"
                    : "+f"(acc[ms][ns][0]), "+f"(acc[ms][ns][1]),
                      "+f"(acc[ms][ns][2]), "+f"(acc[ms][ns][3])
                    : "r"(a_frag[ms][0]), "r"(a_frag[ms][1]),
                      "r"(a_frag[ms][2]), "r"(a_frag[ms][3]),
                      "r"(b_frag[ns][0]), "r"(b_frag[ns][1]));
            }
    }

    // ---- epilogue: S only (P is analytic, no labels/masks here) ----
    float rSreg[4] = {0, 0, 0, 0};

    #pragma unroll
    for (int ns = 0; ns < 8; ns++) {
        int jl = warp_n * 64 + ns * 8 + quad * 2;
        float cs0 = 0.0f, cs1 = 0.0f;
        #pragma unroll
        for (int ms = 0; ms < 2; ms++) {
            #pragma unroll
            for (int e = 0; e < 4; e++) {
                int ridx = ms * 2 + (e >> 1);
                float fv = fmaf(acc[ms][ns][e], K2, -K2);  // log2 scale
                float ex;
                asm("ex2.approx.f32 %0, %1;" : "=f"(ex) : "f"(fv));
                if (diag) {
                    int il = warp_m * 32 + ms * 16 + groupid + (e >> 1) * 8;
                    if (il == jl + (e & 1)) ex = 0.0f;     // exclude self
                }
                rSreg[ridx] += ex;
                if (e & 1) cs1 += ex; else cs0 += ex;
            }
        }
        if (!diag) {
            #pragma unroll
            for (int o = 4; o <= 16; o <<= 1) {
                cs0 += __shfl_xor_sync(0xffffffffu, cs0, o);
                cs1 += __shfl_xor_sync(0xffffffffu, cs1, o);
            }
            if (groupid == 0) {
                atomicAdd(&cS[jl], cs0);
                atomicAdd(&cS[jl + 1], cs1);
            }
        }
    }

    // row side: 4 quad-lanes share each row
    #pragma unroll
    for (int r = 0; r < 4; r++) {
        float s = rSreg[r];
        s += __shfl_xor_sync(0xffffffffu, s, 1);
        s += __shfl_xor_sync(0xffffffffu, s, 2);
        if (quad == 0) {
            int rloc = warp_m * 32 + (r >> 1) * 16 + groupid + (r & 1) * 8;
            atomicAdd(&rS[rloc], s);
        }
    }

    __syncthreads();

    if (tid < 128) {
        atomicAdd(&g_S[iBase + tid], rS[tid]);
        if (!diag) atomicAdd(&g_S[jBase + tid], cS[tid]);
    }
}

// ---------------- final loss (64 blocks x 256) ----------------
// P_i = (f_i . classSum[lab_i] - hist[lab_i]) / T ; cnt_i = hist[lab_i]-1
__global__ void loss_kernel(float* __restrict__ out) {
    __shared__ int hist[128];
    int t = threadIdx.x;
    int warp = t >> 5, lane = t & 31;
    if (t < 128) hist[t] = 0;
    __syncthreads();
    for (int i = t; i < NROWS; i += 256) atomicAdd(&hist[g_labels[i] & 127], 1);
    __syncthreads();

    float wsum = 0.0f;
    #pragma unroll 1
    for (int rr = 0; rr < 16; rr++) {
        int i = blockIdx.x * 128 + warp * 16 + rr;
        int lab = g_labels[i];
        const __nv_bfloat162* f2 = (const __nv_bfloat162*)(g_feats + (size_t)i * DDIM);
        const float4* cs = (const float4*)(g_classSum + lab * DDIM);
        __nv_bfloat162 a = f2[lane * 2], bb = f2[lane * 2 + 1];
        float4 c = cs[lane];
        float d = __low2float(a) * c.x + __high2float(a) * c.y
                + __low2float(bb) * c.z + __high2float(bb) * c.w;
        #pragma unroll
        for (int o = 16; o; o >>= 1) d += __shfl_xor_sync(0xffffffffu, d, o);
        if (lane == 0) {
            float h = (float)hist[lab];
            float P = (d - h) * INV_T;
            wsum += P / (h - 1.0f) - logf(g_S[i] + 1e-12f);
        }
    }
    if (lane == 0) atomicAdd(out, -wsum / (float)NROWS);
}

// ---------------- launch ----------------
extern "C" void kernel_launch(void* const* d_in, const int* in_sizes, int n_in,
                              void* d_out, int out_size) {
    const float* feats = (const float*)d_in[0];
    const unsigned int* labw = (const unsigned int*)d_in[1];

    cudaFuncSetAttribute(gemm_kernel, cudaFuncAttributeMaxDynamicSharedMemorySize,
                         66560);

    prep_norm_kernel<<<NROWS / 8, 256>>>(feats, labw, (float*)d_out);
    classsum_kernel<<<NROWS / 8, 256>>>();
    gemm_kernel<<<2080, 256, 66560>>>();
    loss_kernel<<<64, 256>>>((float*)d_out);
}

// round 7
// speedup vs baseline: 1.3878x; 1.0569x over previous
#include <cuda_runtime.h>
#include <cuda_bf16.h>
#include <math.h>
#include <stdint.h>

#define NROWS 8192
#define DDIM  128
#define INV_T 14.285714285714286f            // 1/0.07 == shift C == row max
#define K2    20.60992915555662f             // log2(e)/0.07

// ---------------- device scratch ----------------
__device__ __nv_bfloat16 g_feats[NROWS * DDIM];   // normalized bf16 features
__device__ float g_S[NROWS];                      // sum_{j!=i} exp(l_ij - C)
__device__ float g_classSum[100 * DDIM];          // per-class feature sums
__device__ int   g_hist[100];                     // class histogram
__device__ int   g_labels[NROWS];

// ---------------- prep: normalize + labels + zero accumulators ----------------
__global__ void prep_norm_kernel(const float* __restrict__ f,
                                 const unsigned int* __restrict__ lw,
                                 float* __restrict__ out) {
    __shared__ int flag;
    int warp = threadIdx.x >> 5;
    int lane = threadIdx.x & 31;
    int row = blockIdx.x * 8 + warp;

    const float4* src = (const float4*)(f + (size_t)row * DDIM);
    float4 v = src[lane];
    float ss = v.x * v.x + v.y * v.y + v.z * v.z + v.w * v.w;
    #pragma unroll
    for (int o = 16; o; o >>= 1) ss += __shfl_xor_sync(0xffffffffu, ss, o);
    float s = 1.0f / fmaxf(sqrtf(ss), 1e-12f);
    __nv_bfloat162* dst = (__nv_bfloat162*)(g_feats + (size_t)row * DDIM);
    dst[lane * 2 + 0] = __floats2bfloat162_rn(v.x * s, v.y * s);
    dst[lane * 2 + 1] = __floats2bfloat162_rn(v.z * s, v.w * s);

    // label dtype sniff: int64 -> odd 32-bit words all zero in first 512 words
    if (threadIdx.x == 0) flag = 0;
    __syncthreads();
    if (lw[2 * threadIdx.x + 1] != 0u) atomicOr(&flag, 1);
    __syncthreads();
    bool is64 = (flag == 0);
    if (threadIdx.x < 8) {
        int i = blockIdx.x * 8 + threadIdx.x;
        g_labels[i] = (int)(is64 ? lw[2 * i] : lw[i]);
        g_S[i] = 0.0f;
    }
    int gid = blockIdx.x * 256 + threadIdx.x;
    if (gid < 100 * DDIM) g_classSum[gid] = 0.0f;
    if (gid < 100) g_hist[gid] = 0;
    if (gid == 0) out[0] = 0.0f;
}

// ---------------- classSum + hist: per-class sums (atomic) ----------------
__global__ void classsum_kernel() {
    int warp = threadIdx.x >> 5;
    int lane = threadIdx.x & 31;
    int i = blockIdx.x * 8 + warp;
    int lab = g_labels[i];
    const __nv_bfloat162* f2 = (const __nv_bfloat162*)(g_feats + (size_t)i * DDIM);
    __nv_bfloat162 a = f2[lane * 2], b = f2[lane * 2 + 1];
    float* cs = g_classSum + lab * DDIM + lane * 4;
    atomicAdd(cs + 0, __low2float(a));
    atomicAdd(cs + 1, __high2float(a));
    atomicAdd(cs + 2, __low2float(b));
    atomicAdd(cs + 3, __high2float(b));
    if (lane == 0) atomicAdd(&g_hist[lab], 1);
}

// ---------------- symmetric fused GEMM + exp-sum epilogue ----------------
// Upper-triangle tiles only (2080 blocks, one 128x128 tile each). Off-diagonal
// tiles accumulate row-side S (anchor i) AND column-side S (anchor j, since
// l_ji = l_ij). 8 warps as 4(m) x 2(n); warp tile 32x64; mma.sync m16n8k16.
__global__ __launch_bounds__(256, 2) void gemm_kernel() {
    extern __shared__ char smem[];
    __nv_bfloat16* As = (__nv_bfloat16*)smem;              // 128x128 bf16, swizzled
    __nv_bfloat16* Bs = (__nv_bfloat16*)(smem + 32768);    // 128x128 bf16, swizzled
    float* rS = (float*)(smem + 65536);                    // row-side S (128)
    float* cS = (float*)(smem + 66048);                    // col-side S (128)

    const int tid  = threadIdx.x;
    const int lane = tid & 31;
    const int warp = tid >> 5;
    const int warp_m = warp >> 1;      // 0..3
    const int warp_n = warp & 1;       // 0..1
    const int groupid = lane >> 2;     // 0..7
    const int quad = lane & 3;         // 0..3

    // ---- decode upper-triangular tile coordinates ----
    int b = blockIdx.x;
    int ti = 0, len = 64;
    while (b >= len) { b -= len; ti++; len--; }
    const int tj = ti + b;
    const bool diag = (ti == tj);
    const int iBase = ti * 128;
    const int jBase = tj * 128;

    // ---- load tiles (XOR-16B swizzle) + zero stats ----
    {
        const uint4* src = (const uint4*)g_feats;   // 16B chunks, 16 per row
        uint4* dstA = (uint4*)As;
        uint4* dstB = (uint4*)Bs;
        #pragma unroll
        for (int it = 0; it < 8; it++) {
            int idx = tid + it * 256;               // 0..2047
            int r = idx >> 4, c = idx & 15;
            int cs = c ^ (r & 7);
            dstA[r * 16 + cs] = src[(size_t)(iBase + r) * 16 + c];
            dstB[r * 16 + cs] = src[(size_t)(jBase + r) * 16 + c];
        }
        if (tid < 128) { rS[tid] = 0.0f; cS[tid] = 0.0f; }
    }
    __syncthreads();

    const unsigned aBase = (unsigned)__cvta_generic_to_shared(As);
    const unsigned bBase = (unsigned)__cvta_generic_to_shared(Bs);

    float acc[2][8][4];
    #pragma unroll
    for (int ms = 0; ms < 2; ms++)
        #pragma unroll
        for (int ns = 0; ns < 8; ns++)
            #pragma unroll
            for (int e = 0; e < 4; e++) acc[ms][ns][e] = 0.0f;

    // ---- main K loop: 8 chunks of k16 ----
    #pragma unroll
    for (int kc = 0; kc < 8; kc++) {
        unsigned a_frag[2][4];
        unsigned b_frag[8][2];

        #pragma unroll
        for (int ms = 0; ms < 2; ms++) {
            int r  = warp_m * 32 + ms * 16 + (lane & 15);
            int c8 = kc * 2 + (lane >> 4);
            unsigned addr = aBase + (unsigned)((r * 16 + (c8 ^ (r & 7))) * 16);
            asm volatile(
                "ldmatrix.sync.aligned.m8n8.x4.shared.b16 {%0,%1,%2,%3}, [%4];"
                : "=r"(a_frag[ms][0]), "=r"(a_frag[ms][1]),
                  "=r"(a_frag[ms][2]), "=r"(a_frag[ms][3])
                : "r"(addr));
        }
        // B: x4 ldmatrix covering a pair of n8 tiles per load
        #pragma unroll
        for (int np = 0; np < 4; np++) {
            int r  = warp_n * 64 + (np * 2 + ((lane >> 4) & 1)) * 8 + (lane & 7);
            int c8 = kc * 2 + ((lane >> 3) & 1);
            unsigned addr = bBase + (unsigned)((r * 16 + (c8 ^ (r & 7))) * 16);
            asm volatile(
                "ldmatrix.sync.aligned.m8n8.x4.shared.b16 {%0,%1,%2,%3}, [%4];"
                : "=r"(b_frag[np * 2][0]), "=r"(b_frag[np * 2][1]),
                  "=r"(b_frag[np * 2 + 1][0]), "=r"(b_frag[np * 2 + 1][1])
                : "r"(addr));
        }
        #pragma unroll
        for (int ms = 0; ms < 2; ms++)
            #pragma unroll
            for (int ns = 0; ns < 8; ns++) {
                asm volatile(
                    "mma.sync.aligned.m16n8k16.row.col.f32.bf16.bf16.f32 "
                    "{%0,%1,%2,%3}, {%4,%5,%6,%7}, {%8,%9}, {%0,%1,%2,%3};"
                    : "+f"(acc[ms][ns][0]), "+f"(acc[ms][ns][1]),
                      "+f"(acc[ms][ns][2]), "+f"(acc[ms][ns][3])
                    : "r"(a_frag[ms][0]), "r"(a_frag[ms][1]),
                      "r"(a_frag[ms][2]), "r"(a_frag[ms][3]),
                      "r"(b_frag[ns][0]), "r"(b_frag[ns][1]));
            }
    }

    // ---- epilogue: S only (P is analytic) ----
    float rSreg[4] = {0, 0, 0, 0};

    #pragma unroll
    for (int ns = 0; ns < 8; ns++) {
        int jl = warp_n * 64 + ns * 8 + quad * 2;
        float cs0 = 0.0f, cs1 = 0.0f;
        #pragma unroll
        for (int ms = 0; ms < 2; ms++) {
            #pragma unroll
            for (int e = 0; e < 4; e++) {
                int ridx = ms * 2 + (e >> 1);
                float fv = fmaf(acc[ms][ns][e], K2, -K2);  // log2 scale
                float ex;
                asm("ex2.approx.f32 %0, %1;" : "=f"(ex) : "f"(fv));
                if (diag) {
                    int il = warp_m * 32 + ms * 16 + groupid + (e >> 1) * 8;
                    if (il == jl + (e & 1)) ex = 0.0f;     // exclude self
                }
                rSreg[ridx] += ex;
                if (e & 1) cs1 += ex; else cs0 += ex;
            }
        }
        if (!diag) {
            #pragma unroll
            for (int o = 4; o <= 16; o <<= 1) {
                cs0 += __shfl_xor_sync(0xffffffffu, cs0, o);
                cs1 += __shfl_xor_sync(0xffffffffu, cs1, o);
            }
            if (groupid == 0) {
                atomicAdd(&cS[jl], cs0);
                atomicAdd(&cS[jl + 1], cs1);
            }
        }
    }

    #pragma unroll
    for (int r = 0; r < 4; r++) {
        float s = rSreg[r];
        s += __shfl_xor_sync(0xffffffffu, s, 1);
        s += __shfl_xor_sync(0xffffffffu, s, 2);
        if (quad == 0) {
            int rloc = warp_m * 32 + (r >> 1) * 16 + groupid + (r & 1) * 8;
            atomicAdd(&rS[rloc], s);
        }
    }

    __syncthreads();

    if (tid < 128) {
        atomicAdd(&g_S[iBase + tid], rS[tid]);
        if (!diag) atomicAdd(&g_S[jBase + tid], cS[tid]);
    }
}

// ---------------- final loss (1024 blocks x 256, warp-per-row) ----------------
// P_i = (f_i . classSum[lab_i] - hist[lab_i]) / T ; cnt_i = hist[lab_i]-1
__global__ void loss_kernel(float* __restrict__ out) {
    __shared__ float wred[8];
    int warp = threadIdx.x >> 5;
    int lane = threadIdx.x & 31;
    int i = blockIdx.x * 8 + warp;

    int lab = g_labels[i];
    const __nv_bfloat162* f2 = (const __nv_bfloat162*)(g_feats + (size_t)i * DDIM);
    const float4* cs = (const float4*)(g_classSum + lab * DDIM);
    __nv_bfloat162 a = f2[lane * 2], bb = f2[lane * 2 + 1];
    float4 c = cs[lane];
    float d = __low2float(a) * c.x + __high2float(a) * c.y
            + __low2float(bb) * c.z + __high2float(bb) * c.w;
    #pragma unroll
    for (int o = 16; o; o >>= 1) d += __shfl_xor_sync(0xffffffffu, d, o);

    if (lane == 0) {
        float h = (float)g_hist[lab];
        float P = (d - h) * INV_T;
        wred[warp] = P / (h - 1.0f) - logf(g_S[i] + 1e-12f);
    }
    __syncthreads();
    if (threadIdx.x == 0) {
        float s = 0.0f;
        #pragma unroll
        for (int w = 0; w < 8; w++) s += wred[w];
        atomicAdd(out, -s / (float)NROWS);
    }
}

// ---------------- launch ----------------
extern "C" void kernel_launch(void* const* d_in, const int* in_sizes, int n_in,
                              void* d_out, int out_size) {
    const float* feats = (const float*)d_in[0];
    const unsigned int* labw = (const unsigned int*)d_in[1];

    cudaFuncSetAttribute(gemm_kernel, cudaFuncAttributeMaxDynamicSharedMemorySize,
                         66560);

    prep_norm_kernel<<<NROWS / 8, 256>>>(feats, labw, (float*)d_out);
    classsum_kernel<<<NROWS / 8, 256>>>();
    gemm_kernel<<<2080, 256, 66560>>>();
    loss_kernel<<<NROWS / 8, 256>>>((float*)d_out);
}

// round 8
// speedup vs baseline: 1.5636x; 1.1267x over previous
#include <cuda_runtime.h>
#include <cuda_bf16.h>
#include <math.h>
#include <stdint.h>

#define NROWS 8192
#define DDIM  128
#define INV_T 14.285714285714286f            // 1/0.07 == shift C == row max
#define K2    20.60992915555662f             // log2(e)/0.07

// ---------------- device scratch ----------------
__device__ __nv_bfloat16 g_feats[NROWS * DDIM];   // normalized bf16 features
__device__ float g_S[NROWS];                      // sum_{j!=i} exp(l_ij - C)
__device__ float g_classSum[100 * DDIM];          // per-class feature sums
__device__ int   g_hist[100];                     // class histogram
__device__ int   g_labels[NROWS];

// ---------------- prep: normalize + labels + zero accumulators ----------------
__global__ void prep_norm_kernel(const float* __restrict__ f,
                                 const unsigned int* __restrict__ lw,
                                 float* __restrict__ out) {
    __shared__ int flag;
    int warp = threadIdx.x >> 5;
    int lane = threadIdx.x & 31;
    int row = blockIdx.x * 8 + warp;

    const float4* src = (const float4*)(f + (size_t)row * DDIM);
    float4 v = src[lane];
    float ss = v.x * v.x + v.y * v.y + v.z * v.z + v.w * v.w;
    #pragma unroll
    for (int o = 16; o; o >>= 1) ss += __shfl_xor_sync(0xffffffffu, ss, o);
    float s = 1.0f / fmaxf(sqrtf(ss), 1e-12f);
    __nv_bfloat162* dst = (__nv_bfloat162*)(g_feats + (size_t)row * DDIM);
    dst[lane * 2 + 0] = __floats2bfloat162_rn(v.x * s, v.y * s);
    dst[lane * 2 + 1] = __floats2bfloat162_rn(v.z * s, v.w * s);

    // label dtype sniff: int64 -> odd 32-bit words all zero in first 512 words
    if (threadIdx.x == 0) flag = 0;
    __syncthreads();
    if (lw[2 * threadIdx.x + 1] != 0u) atomicOr(&flag, 1);
    __syncthreads();
    bool is64 = (flag == 0);
    if (threadIdx.x < 8) {
        int i = blockIdx.x * 8 + threadIdx.x;
        g_labels[i] = (int)(is64 ? lw[2 * i] : lw[i]);
        g_S[i] = 0.0f;
    }
    int gid = blockIdx.x * 256 + threadIdx.x;
    if (gid < 100 * DDIM) g_classSum[gid] = 0.0f;
    if (gid < 100) g_hist[gid] = 0;
    if (gid == 0) out[0] = 0.0f;
}

// ---------------- classSum + hist: per-class sums (atomic) ----------------
__global__ void classsum_kernel() {
    int warp = threadIdx.x >> 5;
    int lane = threadIdx.x & 31;
    int i = blockIdx.x * 8 + warp;
    int lab = g_labels[i];
    const __nv_bfloat162* f2 = (const __nv_bfloat162*)(g_feats + (size_t)i * DDIM);
    __nv_bfloat162 a = f2[lane * 2], b = f2[lane * 2 + 1];
    float* cs = g_classSum + lab * DDIM + lane * 4;
    atomicAdd(cs + 0, __low2float(a));
    atomicAdd(cs + 1, __high2float(a));
    atomicAdd(cs + 2, __low2float(b));
    atomicAdd(cs + 3, __high2float(b));
    if (lane == 0) atomicAdd(&g_hist[lab], 1);
}

// ---------------- symmetric fused GEMM + exp-sum epilogue ----------------
// Upper-triangle tiles; each CTA handles a PAIR of adjacent j-tiles in one
// row-strip (1056 CTAs). A loaded once per CTA; B double-buffered via
// cp.async so tile-1's load overlaps tile-0's compute. Row-side stats
// accumulate across both tiles; col-side flushed per tile.
__global__ __launch_bounds__(256, 2) void gemm_kernel() {
    extern __shared__ char smem[];
    // [0,32K) A ; [32K,64K) B0 ; [64K,96K) B1 ; then rS(512) cS(512)
    float* rS = (float*)(smem + 98304);
    float* cS = (float*)(smem + 98816);

    const int tid  = threadIdx.x;
    const int lane = tid & 31;
    const int warp = tid >> 5;
    const int warp_m = warp >> 1;      // 0..3
    const int warp_n = warp & 1;       // 0..1
    const int groupid = lane >> 2;     // 0..7
    const int quad = lane & 3;         // 0..3

    // ---- decode (row-strip, pair) ----
    int b = blockIdx.x;
    int ti = 0, c = 32;                 // c = ceil((64-ti)/2)
    while (b >= c) { b -= c; ti++; c = (65 - ti) >> 1; }
    const int jt0 = ti + 2 * b;
    const int ntile = (jt0 + 1 < 64) ? 2 : 1;
    const int iBase = ti * 128;

    const unsigned sbase = (unsigned)__cvta_generic_to_shared(smem);

    // ---- async tile loads: A + B0 (group0), B1 (group1) ----
    {
        const uint4* src = (const uint4*)g_feats;   // 16B chunks, 16 per row
        #pragma unroll
        for (int it = 0; it < 8; it++) {
            int idx = tid + it * 256;               // 0..2047
            int r = idx >> 4, cc = idx & 15;
            unsigned soff = (unsigned)((r * 16 + (cc ^ (r & 7))) * 16);
            asm volatile("cp.async.cg.shared.global [%0], [%1], 16;"
                         :: "r"(sbase + soff),
                            "l"(src + (size_t)(iBase + r) * 16 + cc) : "memory");
            asm volatile("cp.async.cg.shared.global [%0], [%1], 16;"
                         :: "r"(sbase + 32768u + soff),
                            "l"(src + (size_t)(jt0 * 128 + r) * 16 + cc) : "memory");
        }
        asm volatile("cp.async.commit_group;" ::: "memory");
        if (ntile == 2) {
            #pragma unroll
            for (int it = 0; it < 8; it++) {
                int idx = tid + it * 256;
                int r = idx >> 4, cc = idx & 15;
                unsigned soff = (unsigned)((r * 16 + (cc ^ (r & 7))) * 16);
                asm volatile("cp.async.cg.shared.global [%0], [%1], 16;"
                             :: "r"(sbase + 65536u + soff),
                                "l"(src + (size_t)((jt0 + 1) * 128 + r) * 16 + cc) : "memory");
            }
            asm volatile("cp.async.commit_group;" ::: "memory");
            asm volatile("cp.async.wait_group 1;" ::: "memory");
        } else {
            asm volatile("cp.async.wait_group 0;" ::: "memory");
        }
        if (tid < 128) { rS[tid] = 0.0f; cS[tid] = 0.0f; }
    }
    __syncthreads();

    float rSreg[4] = {0, 0, 0, 0};

    #pragma unroll 1
    for (int t = 0; t < ntile; t++) {
        const int jBase = (jt0 + t) * 128;
        const bool diag = (b == 0 && t == 0);
        const unsigned aBase = sbase;
        const unsigned bBase = sbase + 32768u + (unsigned)t * 32768u;

        if (t == 1) {
            asm volatile("cp.async.wait_group 0;" ::: "memory");
            __syncthreads();   // Bs1 ready + cS reset visible
        }

        float acc[2][8][4];
        #pragma unroll
        for (int ms = 0; ms < 2; ms++)
            #pragma unroll
            for (int ns = 0; ns < 8; ns++)
                #pragma unroll
                for (int e = 0; e < 4; e++) acc[ms][ns][e] = 0.0f;

        // ---- main K loop: 8 chunks of k16 ----
        #pragma unroll
        for (int kc = 0; kc < 8; kc++) {
            unsigned a_frag[2][4];
            unsigned b_frag[8][2];

            #pragma unroll
            for (int ms = 0; ms < 2; ms++) {
                int r  = warp_m * 32 + ms * 16 + (lane & 15);
                int c8 = kc * 2 + (lane >> 4);
                unsigned addr = aBase + (unsigned)((r * 16 + (c8 ^ (r & 7))) * 16);
                asm volatile(
                    "ldmatrix.sync.aligned.m8n8.x4.shared.b16 {%0,%1,%2,%3}, [%4];"
                    : "=r"(a_frag[ms][0]), "=r"(a_frag[ms][1]),
                      "=r"(a_frag[ms][2]), "=r"(a_frag[ms][3])
                    : "r"(addr));
            }
            #pragma unroll
            for (int np = 0; np < 4; np++) {
                int r  = warp_n * 64 + (np * 2 + ((lane >> 4) & 1)) * 8 + (lane & 7);
                int c8 = kc * 2 + ((lane >> 3) & 1);
                unsigned addr = bBase + (unsigned)((r * 16 + (c8 ^ (r & 7))) * 16);
                asm volatile(
                    "ldmatrix.sync.aligned.m8n8.x4.shared.b16 {%0,%1,%2,%3}, [%4];"
                    : "=r"(b_frag[np * 2][0]), "=r"(b_frag[np * 2][1]),
                      "=r"(b_frag[np * 2 + 1][0]), "=r"(b_frag[np * 2 + 1][1])
                    : "r"(addr));
            }
            #pragma unroll
            for (int ms = 0; ms < 2; ms++)
                #pragma unroll
                for (int ns = 0; ns < 8; ns++) {
                    asm volatile(
                        "mma.sync.aligned.m16n8k16.row.col.f32.bf16.bf16.f32 "
                        "{%0,%1,%2,%3}, {%4,%5,%6,%7}, {%8,%9}, {%0,%1,%2,%3};"
                        : "+f"(acc[ms][ns][0]), "+f"(acc[ms][ns][1]),
                          "+f"(acc[ms][ns][2]), "+f"(acc[ms][ns][3])
                        : "r"(a_frag[ms][0]), "r"(a_frag[ms][1]),
                          "r"(a_frag[ms][2]), "r"(a_frag[ms][3]),
                          "r"(b_frag[ns][0]), "r"(b_frag[ns][1]));
                }
        }

        // ---- epilogue: S only (P is analytic) ----
        #pragma unroll
        for (int ns = 0; ns < 8; ns++) {
            int jl = warp_n * 64 + ns * 8 + quad * 2;
            float cs0 = 0.0f, cs1 = 0.0f;
            #pragma unroll
            for (int ms = 0; ms < 2; ms++) {
                #pragma unroll
                for (int e = 0; e < 4; e++) {
                    int ridx = ms * 2 + (e >> 1);
                    float fv = fmaf(acc[ms][ns][e], K2, -K2);  // log2 scale
                    float ex;
                    asm("ex2.approx.f32 %0, %1;" : "=f"(ex) : "f"(fv));
                    if (diag) {
                        int il = warp_m * 32 + ms * 16 + groupid + (e >> 1) * 8;
                        if (il == jl + (e & 1)) ex = 0.0f;     // exclude self
                    }
                    rSreg[ridx] += ex;
                    if (e & 1) cs1 += ex; else cs0 += ex;
                }
            }
            if (!diag) {
                #pragma unroll
                for (int o = 4; o <= 16; o <<= 1) {
                    cs0 += __shfl_xor_sync(0xffffffffu, cs0, o);
                    cs1 += __shfl_xor_sync(0xffffffffu, cs1, o);
                }
                if (groupid == 0) {
                    atomicAdd(&cS[jl], cs0);
                    atomicAdd(&cS[jl + 1], cs1);
                }
            }
        }

        __syncthreads();
        if (tid < 128 && !diag) {
            atomicAdd(&g_S[jBase + tid], cS[tid]);
            cS[tid] = 0.0f;
        }
    }

    // ---- row-side flush (once per CTA) ----
    #pragma unroll
    for (int r = 0; r < 4; r++) {
        float s = rSreg[r];
        s += __shfl_xor_sync(0xffffffffu, s, 1);
        s += __shfl_xor_sync(0xffffffffu, s, 2);
        if (quad == 0) {
            int rloc = warp_m * 32 + (r >> 1) * 16 + groupid + (r & 1) * 8;
            atomicAdd(&rS[rloc], s);
        }
    }
    __syncthreads();
    if (tid < 128) atomicAdd(&g_S[iBase + tid], rS[tid]);
}

// ---------------- final loss (512 blocks x 256, 2 rows per warp) ----------------
// P_i = (f_i . classSum[lab_i] - hist[lab_i]) / T ; cnt_i = hist[lab_i]-1
__global__ void loss_kernel(float* __restrict__ out) {
    __shared__ float wred[16];
    int warp = threadIdx.x >> 5;
    int lane = threadIdx.x & 31;
    int i0 = blockIdx.x * 16 + warp * 2;
    int i1 = i0 + 1;

    int lab0 = g_labels[i0];
    int lab1 = g_labels[i1];
    const __nv_bfloat162* fa = (const __nv_bfloat162*)(g_feats + (size_t)i0 * DDIM);
    const __nv_bfloat162* fb = (const __nv_bfloat162*)(g_feats + (size_t)i1 * DDIM);
    const float4* csa = (const float4*)(g_classSum + lab0 * DDIM);
    const float4* csb = (const float4*)(g_classSum + lab1 * DDIM);

    __nv_bfloat162 a0 = fa[lane * 2], a1 = fa[lane * 2 + 1];
    __nv_bfloat162 b0 = fb[lane * 2], b1 = fb[lane * 2 + 1];
    float4 c0 = csa[lane];
    float4 c1 = csb[lane];

    float d0 = __low2float(a0) * c0.x + __high2float(a0) * c0.y
             + __low2float(a1) * c0.z + __high2float(a1) * c0.w;
    float d1 = __low2float(b0) * c1.x + __high2float(b0) * c1.y
             + __low2float(b1) * c1.z + __high2float(b1) * c1.w;
    #pragma unroll
    for (int o = 16; o; o >>= 1) {
        d0 += __shfl_xor_sync(0xffffffffu, d0, o);
        d1 += __shfl_xor_sync(0xffffffffu, d1, o);
    }

    if (lane == 0) {
        float h0 = (float)g_hist[lab0];
        float h1 = (float)g_hist[lab1];
        float P0 = (d0 - h0) * INV_T;
        float P1 = (d1 - h1) * INV_T;
        wred[warp * 2]     = P0 / (h0 - 1.0f) - logf(g_S[i0] + 1e-12f);
        wred[warp * 2 + 1] = P1 / (h1 - 1.0f) - logf(g_S[i1] + 1e-12f);
    }
    __syncthreads();
    if (threadIdx.x == 0) {
        float s = 0.0f;
        #pragma unroll
        for (int w = 0; w < 16; w++) s += wred[w];
        atomicAdd(out, -s / (float)NROWS);
    }
}

// ---------------- launch ----------------
extern "C" void kernel_launch(void* const* d_in, const int* in_sizes, int n_in,
                              void* d_out, int out_size) {
    const float* feats = (const float*)d_in[0];
    const unsigned int* labw = (const unsigned int*)d_in[1];

    cudaFuncSetAttribute(gemm_kernel, cudaFuncAttributeMaxDynamicSharedMemorySize,
                         99328);

    prep_norm_kernel<<<NROWS / 8, 256>>>(feats, labw, (float*)d_out);
    classsum_kernel<<<NROWS / 8, 256>>>();
    gemm_kernel<<<1056, 256, 99328>>>();
    loss_kernel<<<NROWS / 16, 256>>>((float*)d_out);
}